// round 7
// baseline (speedup 1.0000x reference)
#include <cuda_runtime.h>

// GRITAttention — counting sort + fused accumulate+GEMM:
//  logit_e = (qa[gsrc] + ka[gdst] + e_emb[e]·wewa + cbias) / 4
//  alpha_e = exp(logit)/sum_{dst}(exp)
//  out[g]  = [accx[g] | acc64[g]] @ [[Wv];[Wev]] + alphasum[g]*(bv+bev)
//  accx/acc64 accumulated straight into SMEM per 64-node block, GEMM from SMEM.

#define DM 128
#define DE 64
#define MAX_NODES 200000
#define MAX_E     600000
#define APAD 196                      // padded K-stride for sA rows (16B aligned)

typedef unsigned long long ull;

// ---------------- device scratch (no allocation allowed) ----------------
__device__ __align__(16) float g_wqa[DM];
__device__ __align__(16) float g_wka[DM];
__device__ __align__(16) float g_wewa[DE];
__device__ float g_cbias;
__device__ int   g_is64;

__device__ __align__(16) float g_qa[MAX_NODES];
__device__ __align__(16) float g_ka[MAX_NODES];
__device__ __align__(16) float g_attsum[MAX_NODES];
__device__ __align__(16) float g_attexp[MAX_E];

// sort structures
__device__ __align__(16) int  g_hist[MAX_NODES];
__device__ __align__(16) int  g_segstart[MAX_NODES];
__device__ __align__(16) int  g_cursor[MAX_NODES];
__device__ __align__(16) int  g_blocksum[1024];
__device__ __align__(16) int4 g_sp[MAX_E];             // {gdst, e, alpha(bits), pad}

// ---------------- helpers ----------------
__device__ __forceinline__ void ffma2(ull& d, ull a, ull b) {
    asm("fma.rn.f32x2 %0, %1, %2, %3;" : "=l"(d) : "l"(a), "l"(b), "l"(d));
}
__device__ __forceinline__ float hadd2(ull v) {
    float lo = __uint_as_float((unsigned)(v & 0xffffffffull));
    float hi = __uint_as_float((unsigned)(v >> 32));
    return lo + hi;
}
__device__ __forceinline__ int ld_idx(const void* p, long long i, int is64) {
    if (is64) return (int)((const long long*)p)[i];
    return ((const int*)p)[i];
}

// ---------------- kernels ----------------

// merged: zero (blocks 0..gridDim-2) + prep + dtype-detect (last block)
__global__ void k_init(const float* __restrict__ Wq, const float* __restrict__ bq,
                       const float* __restrict__ Wk, const float* __restrict__ bk,
                       const float* __restrict__ Wew, const float* __restrict__ bew,
                       const float* __restrict__ Wa, const int* __restrict__ ei,
                       int nodes) {
    if (blockIdx.x == gridDim.x - 1) {
        int t = threadIdx.x;
        if (t < DM) {
            float s1 = 0.f, s2 = 0.f;
            for (int j = 0; j < DM; j++) {
                float w = Wa[j];
                s1 += Wq[t * DM + j] * w;
                s2 += Wk[t * DM + j] * w;
            }
            g_wqa[t] = s1;
            g_wka[t] = s2;
        } else if (t < DM + DE) {
            int r = t - DM;
            float s = 0.f;
            for (int c = 0; c < DM; c++) s += Wew[r * DM + c] * Wa[c];
            g_wewa[r] = s;
        } else if (t == DM + DE) {
            float s = 0.f;
            for (int j = 0; j < DM; j++) s += (bq[j] + bk[j] + bew[j]) * Wa[j];
            g_cbias = s;
        } else if (t == DM + DE + 1) {
            g_is64 = ((ei[1] | ei[3] | ei[5] | ei[7]) == 0) ? 1 : 0;
        }
    } else {
        int i = blockIdx.x * blockDim.x + threadIdx.x;
        int stride = (gridDim.x - 1) * blockDim.x;
        for (int j = i; j < nodes; j += stride) { g_attsum[j] = 0.f; g_hist[j] = 0; }
    }
}

// per-node scalars qa = x·wqa, ka = x·wka  (one warp per FOUR nodes -> MLP 4)
__global__ void k_qaka(const float* __restrict__ x, int nodes) {
    int w = (blockIdx.x * blockDim.x + threadIdx.x) >> 5;
    int lane = threadIdx.x & 31;
    int g0 = w * 4;
    if (g0 >= nodes) return;
    const float4* x4 = (const float4*)x;
    float4 wq = ((const float4*)g_wqa)[lane];
    float4 wk = ((const float4*)g_wka)[lane];
    float pq[4], pk[4];
    int gi[4];
    #pragma unroll
    for (int j = 0; j < 4; j++)
        gi[j] = (g0 + j < nodes) ? g0 + j : g0;
    float4 a[4];
    #pragma unroll
    for (int j = 0; j < 4; j++)
        a[j] = x4[(size_t)gi[j] * 32 + lane];
    #pragma unroll
    for (int j = 0; j < 4; j++) {
        pq[j] = a[j].x * wq.x + a[j].y * wq.y + a[j].z * wq.z + a[j].w * wq.w;
        pk[j] = a[j].x * wk.x + a[j].y * wk.y + a[j].z * wk.z + a[j].w * wk.w;
    }
    #pragma unroll
    for (int off = 16; off; off >>= 1) {
        #pragma unroll
        for (int j = 0; j < 4; j++) {
            pq[j] += __shfl_down_sync(0xffffffffu, pq[j], off);
            pk[j] += __shfl_down_sync(0xffffffffu, pk[j], off);
        }
    }
    if (lane == 0) {
        #pragma unroll
        for (int j = 0; j < 4; j++) {
            if (g0 + j < nodes) { g_qa[g0 + j] = pq[j]; g_ka[g0 + j] = pk[j]; }
        }
    }
}

// pass 1: per edge logit -> exp, denominator per gdst, histogram per gsrc. 8 lanes/edge.
__global__ void k_edge1(const void* __restrict__ ei, const float* __restrict__ emb,
                        const void* __restrict__ bi, int E, int Nn) {
    int gid = blockIdx.x * blockDim.x + threadIdx.x;
    int e = gid >> 3;
    int l = gid & 7;
    bool valid = e < E;
    int ec = valid ? e : 0;
    const float4* e4 = (const float4*)emb;
    float4 a = e4[(size_t)ec * 16 + l * 2];
    float4 b = e4[(size_t)ec * 16 + l * 2 + 1];
    float4 w1 = ((const float4*)g_wewa)[l * 2];
    float4 w2 = ((const float4*)g_wewa)[l * 2 + 1];
    float p = a.x * w1.x + a.y * w1.y + a.z * w1.z + a.w * w1.w
            + b.x * w2.x + b.y * w2.y + b.z * w2.z + b.w * w2.w;
    p += __shfl_down_sync(0xffffffffu, p, 4, 8);
    p += __shfl_down_sync(0xffffffffu, p, 2, 8);
    p += __shfl_down_sync(0xffffffffu, p, 1, 8);
    if (valid && l == 0) {
        int is64 = g_is64;
        int s  = ld_idx(ei, e, is64);
        int d  = ld_idx(ei, (long long)E + e, is64);
        int bb = ld_idx(bi, e, is64);
        int gsrc = bb * Nn + s;
        int gdst = bb * Nn + d;
        float logit = (g_qa[gsrc] + g_ka[gdst] + p + g_cbias) * 0.25f; // 1/sqrt(16)
        float ex = expf(logit);
        g_attexp[e] = ex;
        atomicAdd(&g_attsum[gdst], ex);
        atomicAdd(&g_hist[gsrc], 1);
    }
}

// ---- 3-step exclusive scan of g_hist ----
__global__ void k_scan1(int nodes) {
    __shared__ int s[256];
    int i = blockIdx.x * 256 + threadIdx.x;
    int v = (i < nodes) ? g_hist[i] : 0;
    s[threadIdx.x] = v;
    __syncthreads();
    #pragma unroll
    for (int off = 128; off; off >>= 1) {
        if (threadIdx.x < off) s[threadIdx.x] += s[threadIdx.x + off];
        __syncthreads();
    }
    if (threadIdx.x == 0) g_blocksum[blockIdx.x] = s[0];
}

__global__ void k_scan2(int nb) {
    __shared__ int s[1024];
    int t = threadIdx.x;
    int v = (t < nb) ? g_blocksum[t] : 0;
    s[t] = v;
    __syncthreads();
    #pragma unroll
    for (int off = 1; off < 1024; off <<= 1) {
        int add = (t >= off) ? s[t - off] : 0;
        __syncthreads();
        s[t] += add;
        __syncthreads();
    }
    if (t < nb) g_blocksum[t] = s[t] - v;   // exclusive
}

__global__ void k_scan3(int nodes) {
    __shared__ int s[256];
    int i = blockIdx.x * 256 + threadIdx.x;
    int v = (i < nodes) ? g_hist[i] : 0;
    s[threadIdx.x] = v;
    __syncthreads();
    #pragma unroll
    for (int off = 1; off < 256; off <<= 1) {
        int add = (threadIdx.x >= off) ? s[threadIdx.x - off] : 0;
        __syncthreads();
        s[threadIdx.x] += add;
        __syncthreads();
    }
    if (i < nodes) {
        int start = g_blocksum[blockIdx.x] + s[threadIdx.x] - v;
        g_segstart[i] = start;
        g_cursor[i]   = start;
    }
}

// scatter: per edge, compute alpha, place packed payload into gsrc-sorted slot
__global__ void k_scatter(const void* __restrict__ ei, const void* __restrict__ bi,
                          int E, int Nn) {
    int e = blockIdx.x * blockDim.x + threadIdx.x;
    if (e >= E) return;
    int is64 = g_is64;
    int s  = ld_idx(ei, e, is64);
    int d  = ld_idx(ei, (long long)E + e, is64);
    int bb = ld_idx(bi, e, is64);
    int gsrc = bb * Nn + s;
    int gdst = bb * Nn + d;
    float alpha = g_attexp[e] / (g_attsum[gdst] + 1e-9f);
    int pos = atomicAdd(&g_cursor[gsrc], 1);
    g_sp[pos] = make_int4(gdst, e, __float_as_int(alpha), 0);
}

// fused: phase A accumulates [alpha*x | alpha*emb] per node into SMEM (warp/node),
// phase B does the 64x128x192 GEMM from SMEM with packed f32x2 FMAs.
__global__ void __launch_bounds__(256)
k_accout(const float* __restrict__ x, const float* __restrict__ emb,
         const float* __restrict__ Wv, const float* __restrict__ bv,
         const float* __restrict__ Wev, const float* __restrict__ bev,
         float* __restrict__ out, int nodes) {
    extern __shared__ float smem[];
    float* sA  = smem;                    // 64 rows x APAD
    float* sW  = smem + 64 * APAD;        // 16 x 256 pair-interleaved
    float* sAl = sW + 16 * 256;           // 64 alphasums

    int tid  = threadIdx.x;
    int lane = tid & 31;
    int wid  = tid >> 5;
    int tx   = tid & 31;
    int ty   = tid >> 5;
    int g0   = blockIdx.x * 64;

    const float4* x4 = (const float4*)x;
    const float2* e2 = (const float2*)emb;

    // ---- phase A: each warp accumulates 8 nodes ----
    #pragma unroll 1
    for (int n8 = 0; n8 < 8; n8++) {
        int gl = wid * 8 + n8;
        int g  = g0 + gl;
        float4 ax = make_float4(0.f, 0.f, 0.f, 0.f);
        float2 ae = make_float2(0.f, 0.f);
        float asum = 0.f;
        if (g < nodes) {
            int i   = g_segstart[g];
            int end = g_cursor[g];
            for (; i + 1 < end; i += 2) {
                int4 p0 = __ldg(&g_sp[i]);
                int4 p1 = __ldg(&g_sp[i + 1]);
                float a0 = __int_as_float(p0.z), a1 = __int_as_float(p1.z);
                float4 xv0 = x4[(size_t)p0.x * 32 + lane];
                float4 xv1 = x4[(size_t)p1.x * 32 + lane];
                float2 ev0 = e2[(size_t)p0.y * 32 + lane];
                float2 ev1 = e2[(size_t)p1.y * 32 + lane];
                ax.x += a0 * xv0.x + a1 * xv1.x;
                ax.y += a0 * xv0.y + a1 * xv1.y;
                ax.z += a0 * xv0.z + a1 * xv1.z;
                ax.w += a0 * xv0.w + a1 * xv1.w;
                ae.x += a0 * ev0.x + a1 * ev1.x;
                ae.y += a0 * ev0.y + a1 * ev1.y;
                asum += a0 + a1;
            }
            if (i < end) {
                int4 p = __ldg(&g_sp[i]);
                float a = __int_as_float(p.z);
                float4 xv = x4[(size_t)p.x * 32 + lane];
                float2 ev = e2[(size_t)p.y * 32 + lane];
                ax.x += a * xv.x; ax.y += a * xv.y; ax.z += a * xv.z; ax.w += a * xv.w;
                ae.x += a * ev.x; ae.y += a * ev.y;
                asum += a;
            }
        }
        *(float4*)&sA[gl * APAD + lane * 4] = ax;
        *(float2*)&sA[gl * APAD + 128 + lane * 2] = ae;
        if (lane == 0) sAl[gl] = asum;
    }

    // ---- phase B: GEMM [64 x 192] @ [192 x 128] ----
    ull acc[8][4];
    #pragma unroll
    for (int i = 0; i < 8; i++)
        #pragma unroll
        for (int j = 0; j < 4; j++) acc[i][j] = 0ull;

    for (int kb = 0; kb < 192; kb += 32) {
        // load W chunk (32 x 128) pair-interleaved: sW[k2*256 + 2c + h] = W[kb+2k2+h][c]
        #pragma unroll
        for (int t = 0; t < 16; t++) {
            int i = tid + t * 256;
            int k = i >> 7;
            int c = i & 127;
            int kg = kb + k;
            float v = (kg < 128) ? Wv[kg * DM + c] : Wev[(kg - 128) * DM + c];
            sW[(k >> 1) * 256 + ((c << 1) | (k & 1))] = v;
        }
        __syncthreads();   // also orders phase-A sA stores on first iteration
        #pragma unroll
        for (int k2 = 0; k2 < 16; k2++) {
            ull a2[8];
            #pragma unroll
            for (int i = 0; i < 8; i++)
                a2[i] = *(const ull*)&sA[(ty * 8 + i) * APAD + kb + k2 * 2]; // warp-uniform
            ulonglong2 p0 = *(const ulonglong2*)&sW[k2 * 256 + tx * 8];
            ulonglong2 p1 = *(const ulonglong2*)&sW[k2 * 256 + tx * 8 + 4];
            ull w0 = p0.x, w1 = p0.y, w2 = p1.x, w3 = p1.y;
            #pragma unroll
            for (int i = 0; i < 8; i++) {
                ffma2(acc[i][0], a2[i], w0);
                ffma2(acc[i][1], a2[i], w1);
                ffma2(acc[i][2], a2[i], w2);
                ffma2(acc[i][3], a2[i], w3);
            }
        }
        __syncthreads();
    }

    float4 b1 = *(const float4*)&bv[tx * 4];
    float4 b2 = *(const float4*)&bev[tx * 4];
    float4 bs = make_float4(b1.x + b2.x, b1.y + b2.y, b1.z + b2.z, b1.w + b2.w);
    #pragma unroll
    for (int i = 0; i < 8; i++) {
        int g = g0 + ty * 8 + i;
        if (g >= nodes) break;
        float as = sAl[ty * 8 + i];
        float4 o;
        o.x = hadd2(acc[i][0]) + as * bs.x;
        o.y = hadd2(acc[i][1]) + as * bs.y;
        o.z = hadd2(acc[i][2]) + as * bs.z;
        o.w = hadd2(acc[i][3]) + as * bs.w;
        *(float4*)&out[(size_t)g * DM + tx * 4] = o;
    }
}

// ---------------- launcher ----------------
extern "C" void kernel_launch(void* const* d_in, const int* in_sizes, int n_in,
                              void* d_out, int out_size) {
    const float* x   = (const float*)d_in[0];
    const void*  ei  = d_in[1];
    const float* emb = (const float*)d_in[2];
    const void*  bi  = d_in[3];
    int base = 4;
    if (n_in >= 16 && in_sizes[4] <= 2) base = 5;
    const float* Wq  = (const float*)d_in[base + 0];
    const float* bq  = (const float*)d_in[base + 1];
    const float* Wk  = (const float*)d_in[base + 2];
    const float* bk  = (const float*)d_in[base + 3];
    const float* Wv  = (const float*)d_in[base + 4];
    const float* bv  = (const float*)d_in[base + 5];
    const float* Wew = (const float*)d_in[base + 6];
    const float* bew = (const float*)d_in[base + 7];
    const float* Wev = (const float*)d_in[base + 8];
    const float* bev = (const float*)d_in[base + 9];
    const float* Wa  = (const float*)d_in[base + 10];

    int nodes = in_sizes[0] / DM;   // B*N
    int E     = in_sizes[3];
    int Nn    = nodes / 4;          // N (B = 4)
    int nb    = (nodes + 255) / 256;

    int smem_bytes = (64 * APAD + 16 * 256 + 64) * (int)sizeof(float);
    cudaFuncSetAttribute(k_accout, cudaFuncAttributeMaxDynamicSharedMemorySize, smem_bytes);

    k_init<<<257, 256>>>(Wq, bq, Wk, bk, Wew, bew, Wa, (const int*)ei, nodes);
    k_qaka<<<(nodes / 4 + 7) / 8, 256>>>(x, nodes);
    k_edge1<<<(E + 31) / 32, 256>>>(ei, emb, bi, E, Nn);
    k_scan1<<<nb, 256>>>(nodes);
    k_scan2<<<1, 1024>>>(nb);
    k_scan3<<<nb, 256>>>(nodes);
    k_scatter<<<(E + 255) / 256, 256>>>(ei, bi, E, Nn);
    k_accout<<<(nodes + 63) / 64, 256, smem_bytes>>>(x, emb, Wv, bv, Wev, bev,
                                                     (float*)d_out, nodes);
}

// round 8
// speedup vs baseline: 1.2697x; 1.2697x over previous
#include <cuda_runtime.h>

// GRITAttention — counting sort, unfused high-occupancy accum + smem GEMM:
//  logit_e = (qa[gsrc] + ka[gdst] + e_emb[e]·wewa + cbias) / 4
//  alpha_e = exp(logit)/sum_{dst}(exp)
//  out[g]  = [accx[g] | acc64[g]] @ [[Wv];[Wev]] + alphasum[g]*(bv+bev)

#define DM 128
#define DE 64
#define MAX_NODES 200000
#define MAX_E     600000

typedef unsigned long long ull;

// ---------------- device scratch (no allocation allowed) ----------------
__device__ __align__(16) float g_wqa[DM];
__device__ __align__(16) float g_wka[DM];
__device__ __align__(16) float g_wewa[DE];
__device__ float g_cbias;
__device__ int   g_is64;

__device__ __align__(16) float g_qa[MAX_NODES];
__device__ __align__(16) float g_ka[MAX_NODES];
__device__ __align__(16) float g_attsum[MAX_NODES];
__device__ __align__(16) float g_alphasum[MAX_NODES];
__device__ __align__(16) float g_attexp[MAX_E];
__device__ __align__(16) float g_accx[(size_t)MAX_NODES * DM];
__device__ __align__(16) float g_acc64[(size_t)MAX_NODES * DE];

// sort structures
__device__ __align__(16) int  g_hist[MAX_NODES];
__device__ __align__(16) int  g_segstart[MAX_NODES];
__device__ __align__(16) int  g_cursor[MAX_NODES];
__device__ __align__(16) int  g_blocksum[1024];
__device__ __align__(16) int4 g_sp[MAX_E];             // {gdst, e, alpha(bits), pad}

// ---------------- helpers ----------------
__device__ __forceinline__ void ffma2(ull& d, ull a, ull b) {
    asm("fma.rn.f32x2 %0, %1, %2, %3;" : "=l"(d) : "l"(a), "l"(b), "l"(d));
}
__device__ __forceinline__ float hadd2(ull v) {
    float lo = __uint_as_float((unsigned)(v & 0xffffffffull));
    float hi = __uint_as_float((unsigned)(v >> 32));
    return lo + hi;
}
__device__ __forceinline__ int ld_idx(const void* p, long long i, int is64) {
    if (is64) return (int)((const long long*)p)[i];
    return ((const int*)p)[i];
}

// ---------------- kernels ----------------

// merged: zero (blocks 0..gridDim-2) + prep + dtype-detect (last block)
__global__ void k_init(const float* __restrict__ Wq, const float* __restrict__ bq,
                       const float* __restrict__ Wk, const float* __restrict__ bk,
                       const float* __restrict__ Wew, const float* __restrict__ bew,
                       const float* __restrict__ Wa, const int* __restrict__ ei,
                       int nodes) {
    if (blockIdx.x == gridDim.x - 1) {
        int t = threadIdx.x;
        if (t < DM) {
            float s1 = 0.f, s2 = 0.f;
            for (int j = 0; j < DM; j++) {
                float w = Wa[j];
                s1 += Wq[t * DM + j] * w;
                s2 += Wk[t * DM + j] * w;
            }
            g_wqa[t] = s1;
            g_wka[t] = s2;
        } else if (t < DM + DE) {
            int r = t - DM;
            float s = 0.f;
            for (int c = 0; c < DM; c++) s += Wew[r * DM + c] * Wa[c];
            g_wewa[r] = s;
        } else if (t == DM + DE) {
            float s = 0.f;
            for (int j = 0; j < DM; j++) s += (bq[j] + bk[j] + bew[j]) * Wa[j];
            g_cbias = s;
        } else if (t == DM + DE + 1) {
            g_is64 = ((ei[1] | ei[3] | ei[5] | ei[7]) == 0) ? 1 : 0;
        }
    } else {
        int i = blockIdx.x * blockDim.x + threadIdx.x;
        int stride = (gridDim.x - 1) * blockDim.x;
        for (int j = i; j < nodes; j += stride) { g_attsum[j] = 0.f; g_hist[j] = 0; }
    }
}

// per-node scalars qa = x·wqa, ka = x·wka  (one warp per FOUR nodes -> MLP 4)
__global__ void k_qaka(const float* __restrict__ x, int nodes) {
    int w = (blockIdx.x * blockDim.x + threadIdx.x) >> 5;
    int lane = threadIdx.x & 31;
    int g0 = w * 4;
    if (g0 >= nodes) return;
    const float4* x4 = (const float4*)x;
    float4 wq = ((const float4*)g_wqa)[lane];
    float4 wk = ((const float4*)g_wka)[lane];
    float pq[4], pk[4];
    float4 a[4];
    #pragma unroll
    for (int j = 0; j < 4; j++) {
        int gi = (g0 + j < nodes) ? g0 + j : g0;
        a[j] = x4[(size_t)gi * 32 + lane];
    }
    #pragma unroll
    for (int j = 0; j < 4; j++) {
        pq[j] = a[j].x * wq.x + a[j].y * wq.y + a[j].z * wq.z + a[j].w * wq.w;
        pk[j] = a[j].x * wk.x + a[j].y * wk.y + a[j].z * wk.z + a[j].w * wk.w;
    }
    #pragma unroll
    for (int off = 16; off; off >>= 1) {
        #pragma unroll
        for (int j = 0; j < 4; j++) {
            pq[j] += __shfl_down_sync(0xffffffffu, pq[j], off);
            pk[j] += __shfl_down_sync(0xffffffffu, pk[j], off);
        }
    }
    if (lane == 0) {
        #pragma unroll
        for (int j = 0; j < 4; j++) {
            if (g0 + j < nodes) { g_qa[g0 + j] = pq[j]; g_ka[g0 + j] = pk[j]; }
        }
    }
}

// pass 1: per edge logit -> exp, denominator per gdst, histogram per gsrc. 8 lanes/edge.
__global__ void k_edge1(const void* __restrict__ ei, const float* __restrict__ emb,
                        const void* __restrict__ bi, int E, int Nn) {
    int gid = blockIdx.x * blockDim.x + threadIdx.x;
    int e = gid >> 3;
    int l = gid & 7;
    bool valid = e < E;
    int ec = valid ? e : 0;
    const float4* e4 = (const float4*)emb;
    float4 a = e4[(size_t)ec * 16 + l * 2];
    float4 b = e4[(size_t)ec * 16 + l * 2 + 1];
    float4 w1 = ((const float4*)g_wewa)[l * 2];
    float4 w2 = ((const float4*)g_wewa)[l * 2 + 1];
    float p = a.x * w1.x + a.y * w1.y + a.z * w1.z + a.w * w1.w
            + b.x * w2.x + b.y * w2.y + b.z * w2.z + b.w * w2.w;
    p += __shfl_down_sync(0xffffffffu, p, 4, 8);
    p += __shfl_down_sync(0xffffffffu, p, 2, 8);
    p += __shfl_down_sync(0xffffffffu, p, 1, 8);
    if (valid && l == 0) {
        int is64 = g_is64;
        int s  = ld_idx(ei, e, is64);
        int d  = ld_idx(ei, (long long)E + e, is64);
        int bb = ld_idx(bi, e, is64);
        int gsrc = bb * Nn + s;
        int gdst = bb * Nn + d;
        float logit = (g_qa[gsrc] + g_ka[gdst] + p + g_cbias) * 0.25f; // 1/sqrt(16)
        float ex = expf(logit);
        g_attexp[e] = ex;
        atomicAdd(&g_attsum[gdst], ex);
        atomicAdd(&g_hist[gsrc], 1);
    }
}

// ---- 3-step exclusive scan of g_hist ----
__global__ void k_scan1(int nodes) {
    __shared__ int s[256];
    int i = blockIdx.x * 256 + threadIdx.x;
    int v = (i < nodes) ? g_hist[i] : 0;
    s[threadIdx.x] = v;
    __syncthreads();
    #pragma unroll
    for (int off = 128; off; off >>= 1) {
        if (threadIdx.x < off) s[threadIdx.x] += s[threadIdx.x + off];
        __syncthreads();
    }
    if (threadIdx.x == 0) g_blocksum[blockIdx.x] = s[0];
}

__global__ void k_scan2(int nb) {
    __shared__ int s[1024];
    int t = threadIdx.x;
    int v = (t < nb) ? g_blocksum[t] : 0;
    s[t] = v;
    __syncthreads();
    #pragma unroll
    for (int off = 1; off < 1024; off <<= 1) {
        int add = (t >= off) ? s[t - off] : 0;
        __syncthreads();
        s[t] += add;
        __syncthreads();
    }
    if (t < nb) g_blocksum[t] = s[t] - v;   // exclusive
}

__global__ void k_scan3(int nodes) {
    __shared__ int s[256];
    int i = blockIdx.x * 256 + threadIdx.x;
    int v = (i < nodes) ? g_hist[i] : 0;
    s[threadIdx.x] = v;
    __syncthreads();
    #pragma unroll
    for (int off = 1; off < 256; off <<= 1) {
        int add = (threadIdx.x >= off) ? s[threadIdx.x - off] : 0;
        __syncthreads();
        s[threadIdx.x] += add;
        __syncthreads();
    }
    if (i < nodes) {
        int start = g_blocksum[blockIdx.x] + s[threadIdx.x] - v;
        g_segstart[i] = start;
        g_cursor[i]   = start;
    }
}

// scatter: per edge, compute alpha, place packed payload into gsrc-sorted slot
__global__ void k_scatter(const void* __restrict__ ei, const void* __restrict__ bi,
                          int E, int Nn) {
    int e = blockIdx.x * blockDim.x + threadIdx.x;
    if (e >= E) return;
    int is64 = g_is64;
    int s  = ld_idx(ei, e, is64);
    int d  = ld_idx(ei, (long long)E + e, is64);
    int bb = ld_idx(bi, e, is64);
    int gsrc = bb * Nn + s;
    int gdst = bb * Nn + d;
    float alpha = g_attexp[e] / (g_attsum[gdst] + 1e-9f);
    int pos = atomicAdd(&g_cursor[gsrc], 1);
    g_sp[pos] = make_int4(gdst, e, __float_as_int(alpha), 0);
}

// segmented accumulation: one warp per node, registers only, no atomics, no smem
__global__ void k_accum(const float* __restrict__ x, const float* __restrict__ emb,
                        int nodes) {
    int g = (blockIdx.x * blockDim.x + threadIdx.x) >> 5;
    int lane = threadIdx.x & 31;
    if (g >= nodes) return;
    int i   = g_segstart[g];
    int end = g_cursor[g];
    const float4* x4 = (const float4*)x;
    const float2* e2 = (const float2*)emb;
    float4 ax = make_float4(0.f, 0.f, 0.f, 0.f);
    float2 ae = make_float2(0.f, 0.f);
    float asum = 0.f;
    for (; i + 1 < end; i += 2) {
        int4 p0 = __ldg(&g_sp[i]);
        int4 p1 = __ldg(&g_sp[i + 1]);
        float a0 = __int_as_float(p0.z), a1 = __int_as_float(p1.z);
        float4 xv0 = x4[(size_t)p0.x * 32 + lane];
        float4 xv1 = x4[(size_t)p1.x * 32 + lane];
        float2 ev0 = e2[(size_t)p0.y * 32 + lane];
        float2 ev1 = e2[(size_t)p1.y * 32 + lane];
        ax.x += a0 * xv0.x + a1 * xv1.x;
        ax.y += a0 * xv0.y + a1 * xv1.y;
        ax.z += a0 * xv0.z + a1 * xv1.z;
        ax.w += a0 * xv0.w + a1 * xv1.w;
        ae.x += a0 * ev0.x + a1 * ev1.x;
        ae.y += a0 * ev0.y + a1 * ev1.y;
        asum += a0 + a1;
    }
    if (i < end) {
        int4 p = __ldg(&g_sp[i]);
        float a = __int_as_float(p.z);
        float4 xv = x4[(size_t)p.x * 32 + lane];
        float2 ev = e2[(size_t)p.y * 32 + lane];
        ax.x += a * xv.x; ax.y += a * xv.y; ax.z += a * xv.z; ax.w += a * xv.w;
        ae.x += a * ev.x; ae.y += a * ev.y;
        asum += a;
    }
    ((float4*)g_accx)[(size_t)g * 32 + lane] = ax;
    ((float2*)g_acc64)[(size_t)g * 32 + lane] = ae;
    if (lane == 0) g_alphasum[g] = asum;
}

// final fused GEMM: out[g] = [accx | acc64] @ [[Wv];[Wev]] + alphasum[g]*(bv+bev)
__global__ void __launch_bounds__(256)
k_out(const float* __restrict__ Wv, const float* __restrict__ bv,
      const float* __restrict__ Wev, const float* __restrict__ bev,
      float* __restrict__ out, int nodes) {
    __shared__ float sA[64][36];
    __shared__ float sW[16][256];       // pair-interleaved: sW[k2][2c+h] = W[kb+2k2+h][c]
    int tid = threadIdx.x;
    int tx = tid & 31;
    int ty = tid >> 5;
    int g0 = blockIdx.x * 64;

    ull acc[8][4];
    #pragma unroll
    for (int i = 0; i < 8; i++)
        #pragma unroll
        for (int j = 0; j < 4; j++) acc[i][j] = 0ull;

    for (int kb = 0; kb < 192; kb += 32) {
        #pragma unroll
        for (int t = 0; t < 2; t++) {
            int i = tid + t * 256;
            int m = i >> 3;
            int kq = (i & 7) << 2;
            int kg = kb + kq;
            float4 v;
            if (kg < 128)
                v = *(const float4*)&g_accx[(size_t)(g0 + m) * DM + kg];
            else
                v = *(const float4*)&g_acc64[(size_t)(g0 + m) * DE + (kg - 128)];
            *(float4*)&sA[m][kq] = v;
        }
        #pragma unroll
        for (int t = 0; t < 16; t++) {
            int i = tid + t * 256;
            int k = i >> 7;
            int c = i & 127;
            int kg = kb + k;
            float v = (kg < 128) ? Wv[kg * DM + c] : Wev[(kg - 128) * DM + c];
            sW[k >> 1][(c << 1) | (k & 1)] = v;
        }
        __syncthreads();
        #pragma unroll
        for (int k2 = 0; k2 < 16; k2++) {
            ull a2[8];
            #pragma unroll
            for (int i = 0; i < 8; i++)
                a2[i] = *(const ull*)&sA[ty * 8 + i][k2 * 2];
            ulonglong2 p0 = *(const ulonglong2*)&sW[k2][tx * 8];
            ulonglong2 p1 = *(const ulonglong2*)&sW[k2][tx * 8 + 4];
            ull w0 = p0.x, w1 = p0.y, w2 = p1.x, w3 = p1.y;
            #pragma unroll
            for (int i = 0; i < 8; i++) {
                ffma2(acc[i][0], a2[i], w0);
                ffma2(acc[i][1], a2[i], w1);
                ffma2(acc[i][2], a2[i], w2);
                ffma2(acc[i][3], a2[i], w3);
            }
        }
        __syncthreads();
    }

    float4 b1 = *(const float4*)&bv[tx * 4];
    float4 b2 = *(const float4*)&bev[tx * 4];
    float4 bs = make_float4(b1.x + b2.x, b1.y + b2.y, b1.z + b2.z, b1.w + b2.w);
    #pragma unroll
    for (int i = 0; i < 8; i++) {
        int g = g0 + ty * 8 + i;
        if (g >= nodes) break;
        float as = g_alphasum[g];
        float4 o;
        o.x = hadd2(acc[i][0]) + as * bs.x;
        o.y = hadd2(acc[i][1]) + as * bs.y;
        o.z = hadd2(acc[i][2]) + as * bs.z;
        o.w = hadd2(acc[i][3]) + as * bs.w;
        *(float4*)&out[(size_t)g * DM + tx * 4] = o;
    }
}

// ---------------- launcher ----------------
extern "C" void kernel_launch(void* const* d_in, const int* in_sizes, int n_in,
                              void* d_out, int out_size) {
    const float* x   = (const float*)d_in[0];
    const void*  ei  = d_in[1];
    const float* emb = (const float*)d_in[2];
    const void*  bi  = d_in[3];
    int base = 4;
    if (n_in >= 16 && in_sizes[4] <= 2) base = 5;
    const float* Wq  = (const float*)d_in[base + 0];
    const float* bq  = (const float*)d_in[base + 1];
    const float* Wk  = (const float*)d_in[base + 2];
    const float* bk  = (const float*)d_in[base + 3];
    const float* Wv  = (const float*)d_in[base + 4];
    const float* bv  = (const float*)d_in[base + 5];
    const float* Wew = (const float*)d_in[base + 6];
    const float* bew = (const float*)d_in[base + 7];
    const float* Wev = (const float*)d_in[base + 8];
    const float* bev = (const float*)d_in[base + 9];
    const float* Wa  = (const float*)d_in[base + 10];

    int nodes = in_sizes[0] / DM;   // B*N
    int E     = in_sizes[3];
    int Nn    = nodes / 4;          // N (B = 4)
    int nb    = (nodes + 255) / 256;

    k_init<<<257, 256>>>(Wq, bq, Wk, bk, Wew, bew, Wa, (const int*)ei, nodes);
    k_qaka<<<(nodes / 4 + 7) / 8, 256>>>(x, nodes);
    k_edge1<<<(E + 31) / 32, 256>>>(ei, emb, bi, E, Nn);
    k_scan1<<<nb, 256>>>(nodes);
    k_scan2<<<1, 1024>>>(nb);
    k_scan3<<<nb, 256>>>(nodes);
    k_scatter<<<(E + 255) / 256, 256>>>(ei, bi, E, Nn);
    k_accum<<<(nodes + 7) / 8, 256>>>(x, emb, nodes);
    k_out<<<(nodes + 63) / 64, 256>>>(Wv, bv, Wev, bev, (float*)d_out, nodes);
}